// round 15
// baseline (speedup 1.0000x reference)
#include <cuda_runtime.h>

#define HD     64
#define VOC    64
#define HALF   32
#define BATCH  128
#define SEQLEN 2048

// ---- scratch tables (device globals; no allocation allowed) ----
__device__ __align__(16) float g_ks[VOC * HALF];
__device__ __align__(16) float g_ke[VOC * HALF];
__device__ __align__(16) float g_inv_s[VOC];
__device__ __align__(16) float g_inv_e[VOC];
__device__ __align__(16) float g_Ds[VOC * VOC];   // D[v1][v2] = ks(v1).ks(v2)
__device__ __align__(16) float g_De[VOC * VOC];   // D[v1][v2] = ke(v1).ke(v2)

typedef unsigned long long u64;

// fused per-(mem, v, lane) table: ((D[v][2l], D[v][2l+1]), (k[v][l], inv[v]))
__device__ __align__(16) ulonglong2 g_T[2 * VOC * HALF];

__device__ __forceinline__ u64 mul2(u64 a, u64 b) {
    u64 d;
    asm("mul.rn.f32x2 %0, %1, %2;" : "=l"(d) : "l"(a), "l"(b));
    return d;
}
__device__ __forceinline__ u64 add2(u64 a, u64 b) {
    u64 d;
    asm("add.rn.f32x2 %0, %1, %2;" : "=l"(d) : "l"(a), "l"(b));
    return d;
}
__device__ __forceinline__ u64 pack2(float x, float y) {
    u64 r;
    asm("mov.b64 %0, {%1, %2};" : "=l"(r) : "f"(x), "f"(y));
    return r;
}
__device__ __forceinline__ float2 unpack2(u64 v) {
    float x, y;
    asm("mov.b64 {%0, %1}, %2;" : "=f"(x), "=f"(y) : "l"(v));
    return make_float2(x, y);
}

// ============================================================================
// Kernel A: per-vocab-id table precompute (h depends only on token id).
// W1/W2 staged into shared via wide streaming loads (high MLP) so the MLP
// loops run against LDS latency, not serialized DRAM/L2 round-trips.
// Same FMA order as before -> bit-identical g_ks/g_ke/g_inv tables.
// ============================================================================
__global__ void precompute_kernel(
    const float* __restrict__ embed,
    const float* __restrict__ W1, const float* __restrict__ b1,
    const float* __restrict__ W2, const float* __restrict__ b2,
    const float* __restrict__ ln_g, const float* __restrict__ ln_b,
    const float* __restrict__ Ws, const float* __restrict__ bs,
    const float* __restrict__ We, const float* __restrict__ be)
{
    extern __shared__ float swt[];           // W1s[64*128] + W2s[128*64]
    float* W1s = swt;
    float* W2s = swt + HD * 2 * HD;

    __shared__ float s_e[HD];
    __shared__ float s_a[2 * HD];
    __shared__ float s_x[HD];
    __shared__ float s_h[HD];
    __shared__ float s_kv[2 * HALF];

    const int v = blockIdx.x;
    const int t = threadIdx.x;

    // cooperative wide staging: 2048 float4 each, 128 threads -> 16 each
    {
        const float4* W1g = (const float4*)W1;
        const float4* W2g = (const float4*)W2;
        float4* W1sv = (float4*)W1s;
        float4* W2sv = (float4*)W2s;
        #pragma unroll
        for (int i = t; i < HD * 2 * HD / 4; i += 128) {
            W1sv[i] = W1g[i];
            W2sv[i] = W2g[i];
        }
    }
    if (t < HD) s_e[t] = embed[v * HD + t];
    __syncthreads();

    {   // hidden = relu(e @ W1 + b1), 128 units, one per thread
        float acc = b1[t];
        #pragma unroll
        for (int d = 0; d < HD; d++)
            acc = fmaf(s_e[d], W1s[d * (2 * HD) + t], acc);
        s_a[t] = fmaxf(acc, 0.0f);
    }
    __syncthreads();

    if (t < HD) {   // ff = hidden @ W2 + b2 ; x = e + ff
        float f = b2[t];
        #pragma unroll
        for (int k = 0; k < 2 * HD; k++)
            f = fmaf(s_a[k], W2s[k * HD + t], f);
        s_x[t] = s_e[t] + f;
    }
    __syncthreads();

    if (t < HD) {   // LayerNorm (redundant per thread — tiny)
        float mu = 0.0f;
        #pragma unroll
        for (int d = 0; d < HD; d++) mu += s_x[d];
        mu *= (1.0f / HD);
        float var = 0.0f;
        #pragma unroll
        for (int d = 0; d < HD; d++) {
            float dd = s_x[d] - mu;
            var = fmaf(dd, dd, var);
        }
        var *= (1.0f / HD);
        float r = 1.0f / sqrtf(var + 1e-5f);
        s_h[t] = fmaf((s_x[t] - mu) * r, ln_g[t], ln_b[t]);
    }
    __syncthreads();

    if (t < HALF) {             // k_sem = h @ Ws + bs
        float k = bs[t];
        #pragma unroll
        for (int d = 0; d < HD; d++)
            k = fmaf(s_h[d], Ws[d * HALF + t], k);
        g_ks[v * HALF + t] = k;
        s_kv[t] = k;
    } else if (t < 2 * HALF) {  // k_epi = h @ We + be
        const int j = t - HALF;
        float k = be[j];
        #pragma unroll
        for (int d = 0; d < HD; d++)
            k = fmaf(s_h[d], We[d * HALF + j], k);
        g_ke[v * HALF + j] = k;
        s_kv[t] = k;
    }
    __syncthreads();

    if (t == 0) {               // 1/(k.k + 1e-6)
        float den = 1e-6f;
        #pragma unroll
        for (int j = 0; j < HALF; j++) den = fmaf(s_kv[j], s_kv[j], den);
        g_inv_s[v] = 1.0f / den;
    } else if (t == 1) {
        float den = 1e-6f;
        #pragma unroll
        for (int j = 0; j < HALF; j++) den = fmaf(s_kv[HALF + j], s_kv[HALF + j], den);
        g_inv_e[v] = 1.0f / den;
    }
}

#define PRE_SMEM_BYTES (HD * 2 * HD * 4 * 2)   // W1s + W2s = 64 KB

// ============================================================================
// Kernel A2: token-pair dot tables + the packed T table the scan consumes:
//   T[m][v][l] = ((D[v][2l], D[v][2l+1]), (k_m[v][l], inv_m[v]))
// ============================================================================
__global__ void dots_kernel()
{
    const int v1  = blockIdx.x;
    const int tid = threadIdx.x;
    const int v2  = tid & 63;
    const int mem = tid >> 6;

    __shared__ float s_drow[2][VOC];

    const float* tab = mem ? g_ke : g_ks;
    float d = 0.0f;
    #pragma unroll
    for (int j = 0; j < HALF; j++)
        d = fmaf(tab[v1 * HALF + j], tab[v2 * HALF + j], d);
    (mem ? g_De : g_Ds)[v1 * VOC + v2] = d;
    s_drow[mem][v2] = d;
    __syncthreads();

    const int l = tid & 63;
    if (l < HALF) {
        const float kl = (mem ? g_ke : g_ks)[v1 * HALF + l];
        const float iv = (mem ? g_inv_e : g_inv_s)[v1];
        ulonglong2 e;
        e.x = pack2(s_drow[mem][2 * l], s_drow[mem][2 * l + 1]);
        e.y = pack2(kl, iv);
        g_T[mem * (VOC * HALF) + v1 * HALF + l] = e;
    }
}

// ============================================================================
// Kernel B: backward adjoint scan, TOKEN-PAIR steps. (UNCHANGED from R14 —
// protecting the 47.2 baseline; per-token issue ~13.5 instr is near the
// algorithm's wall.)
// Homogeneous recursion (query folded into S' init):
//   d_t = -S'_{t+1}[v_t],  dd_t = wiv_t d_t,  S'_t = S'_{t+1} + dd_t D[v_t,:]
//   S'_2048 = -Dq,  ctx = sum_t wkl_t d_t.
// Pair (a,b) = (t, t-1): both next-pair S lookups are shfl'd AFTER this
// pair's axpy (exact post-update reads -> NO cross-pair corrections); the
// only in-pair coupling is e_b = fma(dd_a, D[v_a,v_b], Rb).
// Signs folded into negated premultiplied weights (nwkl, nwiv).
//
// 256 threads: warp 0 = sem, warp 1 = epi; warps 2-7 preamble-only (exit).
// ============================================================================
__global__ void __launch_bounds__(256, 1) scan_kernel(
    const int* __restrict__ seq,
    const float* __restrict__ Wo,
    const float* __restrict__ bo,
    float* __restrict__ out)
{
    extern __shared__ int smem_raw[];
    int*        s_tokp = smem_raw;                         // 16 pad + 2048
    int*        s_tok  = s_tokp + 16;
    float*      s_D    = (float*)(s_tok + SEQLEN);         // 2 * 4096
    ulonglong2* s_T    = (ulonglong2*)(s_D + 2 * VOC * VOC); // 2*64*32 entries
    float*      s_ctx  = (float*)(s_T + 2 * VOC * HALF);   // 64

    const int b    = blockIdx.x;
    const int tid  = threadIdx.x;
    const int wid  = tid >> 5;
    const int mem  = wid & 1;                 // valid for wid 0,1
    const int lane = tid & 31;

    // ---- preamble: pure wide copies (8 warps cooperate) ----
    {
        const int4* seq4 = (const int4*)(seq + b * SEQLEN);
        int4* tok4 = (int4*)s_tok;
        #pragma unroll
        for (int i = tid; i < SEQLEN / 4; i += 256)
            tok4[i] = seq4[i];
        if (tid < 16) s_tokp[tid] = 0;        // pad: v = 0 (dead prefetch)

        float4* D4 = (float4*)s_D;
        const float4* gDs4 = (const float4*)g_Ds;
        const float4* gDe4 = (const float4*)g_De;
        #pragma unroll
        for (int i = tid; i < VOC * VOC / 4; i += 256) {
            D4[i]                 = gDs4[i];
            D4[VOC * VOC / 4 + i] = gDe4[i];
        }
        #pragma unroll
        for (int i = tid; i < 2 * VOC * HALF; i += 256)
            s_T[i] = g_T[i];
    }
    __syncthreads();

    if (wid >= 2) return;   // preamble helpers done (exited threads satisfy bar)

    const char* Db = (const char*)(s_D + mem * (VOC * VOC)); // + v*256 + v2*4
    const char* Tb = (const char*)(s_T + mem * (VOC * HALF)) + lane * 16; // + v*512

    // ---- prologue ----
    const int vq  = s_tok[2047];              // query token id (= pair-0 a)
    const int v46 = s_tok[2046];              // pair-0 b
    int o_a1 = s_tok[2045], o_b1 = s_tok[2044];   // pair 1
    int o_a2 = s_tok[2043], o_b2 = s_tok[2042];   // pair 2

    // S' init: S'_2048[v] = -D[v][vq]
    const char* Dqcol = Db + vq * 4;
    float Slo = -*(const float*)(Dqcol + (2 * lane) * 256);
    float Shi = -*(const float*)(Dqcol + (2 * lane + 1) * 256);

    // pair 0 = (2047 dummy, 2046)
    float Ra = 0.0f;                                          // unused (nwA=0)
    float Rb = -*(const float*)(Dqcol + v46 * 256);           // S'_2048[v46]
    float Dab = *(const float*)(Db + vq * 256 + v46 * 4);     // D[vq][v46]

    const ulonglong2 T47 = *(const ulonglong2*)(Tb + vq * 512);
    const ulonglong2 T46 = *(const ulonglong2*)(Tb + v46 * 512);
    float2 DrA = unpack2(T47.x);
    float2 DrB = unpack2(T46.x);

    const float wB0 = mem ? (2047.0f / 2048.0f) : 1.0f;
    float nwklA = 0.0f, nwivA = 0.0f;         // token 2047: dummy weight 0
    const float2 T46hi = unpack2(T46.y);
    float nwklB = -T46hi.x * wB0;
    float nwivB = -T46hi.y * wB0;

    // counters hold NEXT pair's negated weights (packed same value twice)
    u64 nwa2p, nwb2p, inc2p;
    if (mem) {
        nwa2p = pack2(-2046.0f / 2048.0f, -2046.0f / 2048.0f);
        nwb2p = pack2(-2045.0f / 2048.0f, -2045.0f / 2048.0f);
        inc2p = pack2(2.0f / 2048.0f, 2.0f / 2048.0f);
    } else {
        nwa2p = pack2(-1.0f, -1.0f);
        nwb2p = pack2(-1.0f, -1.0f);
        inc2p = 0ull;
    }

    ulonglong2 T_a1 = *(const ulonglong2*)(Tb + o_a1 * 512);  // pair-1 T
    ulonglong2 T_b1 = *(const ulonglong2*)(Tb + o_b1 * 512);

    int4 Q  = *(const int4*)(s_tok + 2040);   // tokens [2040..2043]
    int4 Qn = Q;
    const int* qptr = s_tok + 2036;           // next refill

    float ctx = 0.0f;

#define PSTEP(INSA, INSB, LOADQ) do {                                        \
    /* (1) current pair math (signs folded into negated premuls) */          \
    const float dd_a = nwivA * Ra;                                           \
    ctx = fmaf(Ra, nwklA, ctx);                                              \
    const float e_b = fmaf(dd_a, Dab, Rb);                                   \
    const float dd_b = nwivB * e_b;                                          \
    ctx = fmaf(e_b, nwklB, ctx);                                             \
    /* (2) axpy: S' += dd_a DrowA + dd_b DrowB */                            \
    Slo = fmaf(dd_a, DrA.x, Slo);                                            \
    Shi = fmaf(dd_a, DrA.y, Shi);                                            \
    Slo = fmaf(dd_b, DrB.x, Slo);                                            \
    Shi = fmaf(dd_b, DrB.y, Shi);                                            \
    /* (3) shfl lookups for NEXT pair (exact post-axpy reads) */             \
    const float sva = (o_a1 & 1) ? Shi : Slo;                                \
    const float svb = (o_b1 & 1) ? Shi : Slo;                                \
    const float Ra_n = __shfl_sync(0xffffffffu, sva, o_a1 >> 1);             \
    const float Rb_n = __shfl_sync(0xffffffffu, svb, o_b1 >> 1);             \
    if (LOADQ) { Qn = *(const int4*)qptr; qptr -= 4; }                       \
    /* (4) T prefetch for pair+2 (addresses 1 iter old) */                   \
    const ulonglong2 Ta_n = *(const ulonglong2*)(Tb + o_a2 * 512);           \
    const ulonglong2 Tb_n = *(const ulonglong2*)(Tb + o_b2 * 512);           \
    /* (5) in-pair D entry for next pair */                                  \
    const float Dab_n = *(const float*)(Db + o_a1 * 256 + o_b1 * 4);         \
    /* (6) premuls + Drows for next pair from last iter's T loads */         \
    const u64 wpa = mul2(T_a1.y, nwa2p);                                     \
    const u64 wpb = mul2(T_b1.y, nwb2p);                                     \
    nwa2p = add2(nwa2p, inc2p);                                              \
    nwb2p = add2(nwb2p, inc2p);                                              \
    const float2 wau = unpack2(wpa);                                         \
    const float2 wbu = unpack2(wpb);                                         \
    const float2 drA_n = unpack2(T_a1.x);                                    \
    const float2 drB_n = unpack2(T_b1.x);                                    \
    /* (7) rotate */                                                         \
    Ra = Ra_n; Rb = Rb_n; Dab = Dab_n;                                       \
    nwklA = wau.x; nwivA = wau.y;                                            \
    nwklB = wbu.x; nwivB = wbu.y;                                            \
    DrA = drA_n; DrB = drB_n;                                                \
    T_a1 = Ta_n; T_b1 = Tb_n;                                                \
    o_a1 = o_a2; o_b1 = o_b2;                                                \
    o_a2 = (INSA); o_b2 = (INSB);                                            \
} while (0)

    for (int it = 0; it < 1024; it += 2) {
        PSTEP(Q.y, Q.x, 1);      // even iter: inserts pair from Q.y/Q.x
        PSTEP(Qn.w, Qn.z, 0);    // odd iter
        Q = Qn;
    }
#undef PSTEP

    s_ctx[mem * HALF + lane] = ctx;
    __syncthreads();

    // out[b] = [ctx_s, ctx_e] @ Wo + bo   (64 threads, one column each)
    {
        float o = bo[tid];
        #pragma unroll
        for (int i = 0; i < 2 * HALF; i++)
            o = fmaf(s_ctx[i], Wo[i * VOC + tid], o);
        out[b * VOC + tid] = o;
    }
}

// ============================================================================
// Launch. Inputs in metadata order:
// 0:seq 1:embed 2:W1 3:b1 4:W2 5:b2 6:ln_g 7:ln_b 8:Ws 9:bs 10:We 11:be 12:Wo 13:bo
// ============================================================================
// Byte-accurate layout:
//   tok pad+ring: (16 + SEQLEN) * 4 =  8256
//   s_D:          2*VOC*VOC * 4     = 32768
//   s_T:          2*VOC*HALF * 16   = 65536
//   s_ctx:        VOC * 4           =   256
#define SCAN_SMEM_BYTES ((16 + SEQLEN) * 4 + 2*VOC*VOC*4 + 2*VOC*HALF*16 + VOC*4)

extern "C" void kernel_launch(void* const* d_in, const int* in_sizes, int n_in,
                              void* d_out, int out_size)
{
    const int*   seq   = (const int*)  d_in[0];
    const float* embed = (const float*)d_in[1];
    const float* W1    = (const float*)d_in[2];
    const float* b1    = (const float*)d_in[3];
    const float* W2    = (const float*)d_in[4];
    const float* b2    = (const float*)d_in[5];
    const float* ln_g  = (const float*)d_in[6];
    const float* ln_b  = (const float*)d_in[7];
    const float* Ws    = (const float*)d_in[8];
    const float* bs    = (const float*)d_in[9];
    const float* We    = (const float*)d_in[10];
    const float* be    = (const float*)d_in[11];
    const float* Wo    = (const float*)d_in[12];
    const float* bo    = (const float*)d_in[13];

    cudaFuncSetAttribute(precompute_kernel,
                         cudaFuncAttributeMaxDynamicSharedMemorySize,
                         PRE_SMEM_BYTES);
    cudaFuncSetAttribute(scan_kernel,
                         cudaFuncAttributeMaxDynamicSharedMemorySize,
                         SCAN_SMEM_BYTES);

    precompute_kernel<<<VOC, 128, PRE_SMEM_BYTES>>>(embed, W1, b1, W2, b2,
                                                    ln_g, ln_b, Ws, bs, We, be);
    dots_kernel<<<VOC, 128>>>();
    scan_kernel<<<BATCH, 256, SCAN_SMEM_BYTES>>>(seq, Wo, bo, (float*)d_out);
}